// round 14
// baseline (speedup 1.0000x reference)
#include <cuda_runtime.h>
#include <cuda_fp16.h>
#include <math.h>
#include <stdint.h>

#define N_MAX 4096
#define D_DIM 1024
#define BTM 128                                // tile rows (i)
#define BTN 64                                 // tile cols (j)
#define BK 64
#define STRIDE 72                              // fp16 elems per smem row (64 data + 8 pad)
#define ROWB (STRIDE * 2)                      // 144 bytes per row
#define STAGE_ROWS (BTM + BTN)                 // 192 (A rows then B rows)
#define STAGE_BYTES (STAGE_ROWS * ROWB)        // 27648
#define NSTAGE 2
#define SMEM_DYN (NSTAGE * STAGE_BYTES)        // 55296
#define NCHUNK (D_DIM / BK)                    // 16

// Per-row accumulators: [0]=pos_logit [1]=neg_logit [2]=pos_beta [3]=neg_beta
//                       [4]=pos_d     [5]=neg_d     [6]=pos_cnt  [7]=neg_cnt
__device__ float g_acc[N_MAX * 8];
__device__ float g_sq[N_MAX];
__device__ __half g_h[N_MAX * D_DIM];
__device__ unsigned int g_ticket;

// ---------------------------------------------------------------------------
__device__ __forceinline__ uint32_t smem_u32(const void* p) {
    uint32_t a;
    asm("{ .reg .u64 t; cvta.to.shared.u64 t, %1; cvt.u32.u64 %0, t; }" : "=r"(a) : "l"(p));
    return a;
}
__device__ __forceinline__ void cp16(uint32_t dst, const void* src) {
    asm volatile("cp.async.cg.shared.global [%0], [%1], 16;" :: "r"(dst), "l"(src) : "memory");
}
__device__ __forceinline__ void ldsm4(uint32_t& r0, uint32_t& r1, uint32_t& r2, uint32_t& r3,
                                      uint32_t addr) {
    asm volatile("ldmatrix.sync.aligned.m8n8.x4.shared.b16 {%0,%1,%2,%3}, [%4];"
                 : "=r"(r0), "=r"(r1), "=r"(r2), "=r"(r3) : "r"(addr));
}
__device__ __forceinline__ void mma16816(float* c, const uint32_t* a, const uint32_t* b) {
    asm volatile(
        "mma.sync.aligned.m16n8k16.row.col.f32.f16.f16.f32 "
        "{%0,%1,%2,%3}, {%4,%5,%6,%7}, {%8,%9}, {%0,%1,%2,%3};"
        : "+f"(c[0]), "+f"(c[1]), "+f"(c[2]), "+f"(c[3])
        : "r"(a[0]), "r"(a[1]), "r"(a[2]), "r"(a[3]), "r"(b[0]), "r"(b[1]));
}

// ---------------------------------------------------------------------------
// prep: fp16 convert, row norms, zero accumulators + ticket.
// ---------------------------------------------------------------------------
__global__ void prep_kernel(const float* __restrict__ X, int n, int d) {
    const int w = threadIdx.x >> 5;
    const int lane = threadIdx.x & 31;
    const int r = blockIdx.x * 8 + w;
    if (blockIdx.x == 0 && threadIdx.x == 0) g_ticket = 0u;
    if (r >= n) return;
    const float4* xr = (const float4*)(X + (size_t)r * d);

    float4 v[8];
#pragma unroll
    for (int i = 0; i < 8; i++) v[i] = xr[lane + i * 32];

    float s = 0.f;
#pragma unroll
    for (int i = 0; i < 8; i++) {
        s = fmaf(v[i].x, v[i].x, s);
        s = fmaf(v[i].y, v[i].y, s);
        s = fmaf(v[i].z, v[i].z, s);
        s = fmaf(v[i].w, v[i].w, s);
    }

#pragma unroll
    for (int i = 0; i < 8; i++) {
        __half h[4] = {__float2half(v[i].x), __float2half(v[i].y),
                       __float2half(v[i].z), __float2half(v[i].w)};
        *(ushort4*)&g_h[(size_t)r * d + (lane + i * 32) * 4] = *(ushort4*)h;
    }

#pragma unroll
    for (int o = 16; o > 0; o >>= 1) s += __shfl_xor_sync(0xffffffffu, s, o);
    if (lane == 0) g_sq[r] = s;
    if (lane < 8) g_acc[r * 8 + lane] = 0.f;
}

// ---------------------------------------------------------------------------
// pair kernel: 128x64 tiles (bj >= 2*bi; strict gj>gi mask in the 2 straddle
// tiles per bi => every unordered pair counted exactly once, both sides
// accumulated). 32x32 warp tiles (4x2 warp grid) -> 32 accum regs/thread,
// 3 CTAs/SM. 2-stage cp.async ring, barrier per BK=64 chunk.
// ---------------------------------------------------------------------------
__global__ __launch_bounds__(256, 3) void pair_kernel(const int* __restrict__ Tg, int nbj,
                                                      float* __restrict__ out, int n) {
    extern __shared__ __align__(16) char smem[];

    // decode: for bi, bj ranges over [2*bi, nbj)
    int t = blockIdx.x, bi = 0;
    while (t >= nbj - 2 * bi) { t -= nbj - 2 * bi; bi++; }
    const int bj = 2 * bi + t;
    const bool strad = (t < 2);
    const int i0 = bi * BTM, j0 = bj * BTN;

    const int tid = threadIdx.x;
    const int lane = tid & 31;
    const int wid = tid >> 5;
    const int wm = wid & 3;        // warp row: 32 rows each (4 groups)
    const int wn = wid >> 2;       // warp col: 32 cols each (2 groups)

    const uint32_t sb = smem_u32(smem);

    // load geometry: 192 rows x 8 quads = 1536 cp16, 6 per thread
    uint32_t so[6], goff[6];
#pragma unroll
    for (int it = 0; it < 6; it++) {
        const int u = tid + it * 256;
        const int row = u >> 3, q = u & 7;
        so[it] = (uint32_t)(row * ROWB + q * 16);
        goff[it] = (row < BTM)
                       ? ((uint32_t)(i0 + row) * D_DIM + q * 8) * 2u
                       : ((uint32_t)(j0 + row - BTM) * D_DIM + q * 8) * 2u;
    }

    float cfr[2][4][4];
#pragma unroll
    for (int a = 0; a < 2; a++)
#pragma unroll
        for (int b = 0; b < 4; b++)
#pragma unroll
            for (int c = 0; c < 4; c++) cfr[a][b][c] = 0.f;

    auto issue = [&](int c) {
        const uint32_t k0b = (uint32_t)(c * BK) * 2u;
        const uint32_t st = sb + (uint32_t)(c & (NSTAGE - 1)) * STAGE_BYTES;
#pragma unroll
        for (int it = 0; it < 6; it++)
            cp16(st + so[it], (const char*)g_h + (goff[it] + k0b));
        asm volatile("cp.async.commit_group;" ::: "memory");
    };

    issue(0);
#pragma unroll 1
    for (int c = 0; c < NCHUNK; c++) {
        asm volatile("cp.async.wait_group 0;" ::: "memory");   // own cp for chunk c landed
        __syncthreads();                                       // publish + WAR guard
        if (c + 1 < NCHUNK) issue(c + 1);                      // overlaps compute(c)

        const uint32_t st = sb + (uint32_t)(c & (NSTAGE - 1)) * STAGE_BYTES;
        const uint32_t aB = st, bB = st + (uint32_t)(BTM * ROWB);
        const int gl = lane >> 3;
        const uint32_t aRow = (uint32_t)(wm * 32 + (lane & 15)) * ROWB;
        const uint32_t bRow = (uint32_t)(wn * 32 + ((gl >> 1) << 3) + (lane & 7)) * ROWB;
        const uint32_t aKo = (uint32_t)((lane >> 4) << 3) * 2;
        const uint32_t bKo = (uint32_t)((gl & 1) << 3) * 2;
#pragma unroll
        for (int s = 0; s < 4; s++) {                          // 4 k16 steps per chunk
            const uint32_t k0 = (uint32_t)(s * 16) * 2;
            uint32_t af[2][4], bf[4][2];
#pragma unroll
            for (int mt = 0; mt < 2; mt++) {
                const uint32_t ro = aRow + (uint32_t)(mt * 16) * ROWB + k0 + aKo;
                ldsm4(af[mt][0], af[mt][1], af[mt][2], af[mt][3], aB + ro);
            }
#pragma unroll
            for (int g = 0; g < 2; g++) {
                const uint32_t ro = bRow + (uint32_t)(g * 16) * ROWB + k0 + bKo;
                ldsm4(bf[2 * g][0], bf[2 * g][1], bf[2 * g + 1][0], bf[2 * g + 1][1], bB + ro);
            }
#pragma unroll
            for (int mt = 0; mt < 2; mt++)
#pragma unroll
                for (int nt = 0; nt < 4; nt++) mma16816(cfr[mt][nt], af[mt], bf[nt]);
        }
    }
    __syncthreads();

    // ---------------- epilogue (aliases the tile smem) ----------------
    float* sacc_i = (float*)smem;          // 1024 f
    float* sacc_j = sacc_i + 1024;         // 512 f
    float* ssqi = sacc_j + 512;            // 128 f
    float* ssqj = ssqi + 128;              // 64 f
    int* sti = (int*)(ssqj + 64);          // 128 i
    int* stj = sti + 128;                  // 64 i

    for (int v = tid; v < 1536; v += 256) sacc_i[v] = 0.f;
    if (tid < 128) {
        ssqi[tid] = g_sq[i0 + tid];
        sti[tid] = Tg[i0 + tid];
    } else if (tid < 192) {
        const int q = tid - 128;
        ssqj[q] = g_sq[j0 + q];
        stj[q] = Tg[j0 + q];
    }
    __syncthreads();

    const float E2 = 7.3890560989306495f;
    const float E4 = 54.598150033144236f;
    const int qrow = lane >> 2, qcol = lane & 3;

#define CELL(GI, GJ, DOT, SQI, SQJ, SAME, KP)                                        \
    {                                                                                \
        float d2 = fmaf(-2.f, (DOT), (SQI) + (SQJ));                                 \
        float dist = sqrtf(fmaxf(d2, 1e-12f));                                       \
        float tt = __expf(20.f * (1.f - dist));                                      \
        float ea = tt * tt;                                                          \
        if (KP) {                                                                    \
            if (SAME) {                                                              \
                a0 += ea; a1 += __fdividef(E4, tt); a2 += dist; a3 += 1.f;           \
            } else {                                                                 \
                b0 += ea; b1 += E2 * tt; b2 += dist; b3 += 1.f;                      \
            }                                                                        \
        }                                                                            \
    }

#define RED8(OFF)                                                 \
    {                                                             \
        a0 += __shfl_xor_sync(0xffffffffu, a0, OFF);              \
        a1 += __shfl_xor_sync(0xffffffffu, a1, OFF);              \
        a2 += __shfl_xor_sync(0xffffffffu, a2, OFF);              \
        a3 += __shfl_xor_sync(0xffffffffu, a3, OFF);              \
        b0 += __shfl_xor_sync(0xffffffffu, b0, OFF);              \
        b1 += __shfl_xor_sync(0xffffffffu, b1, OFF);              \
        b2 += __shfl_xor_sync(0xffffffffu, b2, OFF);              \
        b3 += __shfl_xor_sync(0xffffffffu, b3, OFF);              \
    }

    // i-oriented pass
#pragma unroll
    for (int mt = 0; mt < 2; mt++)
#pragma unroll
        for (int h = 0; h < 2; h++) {
            const int il = wm * 32 + mt * 16 + h * 8 + qrow;
            const int gi = i0 + il;
            const float sqi = ssqi[il];
            const int ti = sti[il];
            float a0 = 0, a1 = 0, a2 = 0, a3 = 0, b0 = 0, b1 = 0, b2 = 0, b3 = 0;
#pragma unroll
            for (int nt = 0; nt < 4; nt++)
#pragma unroll
                for (int col = 0; col < 2; col++) {
                    const int jl = wn * 32 + nt * 8 + 2 * qcol + col;
                    const int gj = j0 + jl;
                    const bool kp = (!strad) || (gj > gi);
                    CELL(gi, gj, cfr[mt][nt][h * 2 + col], sqi, ssqj[jl],
                         (ti == stj[jl]), kp);
                }
            RED8(1);
            RED8(2);
            if (qcol == 0) {
                float* s = &sacc_i[il * 8];
                atomicAdd(s + 0, a0); atomicAdd(s + 1, b0);
                atomicAdd(s + 2, a1); atomicAdd(s + 3, b1);
                atomicAdd(s + 4, a2); atomicAdd(s + 5, b2);
                atomicAdd(s + 6, a3); atomicAdd(s + 7, b3);
            }
        }

    // j-oriented pass (symmetric contribution; every kept pair feeds j too)
#pragma unroll
    for (int nt = 0; nt < 4; nt++)
#pragma unroll
        for (int col = 0; col < 2; col++) {
            const int jl = wn * 32 + nt * 8 + 2 * qcol + col;
            const int gj = j0 + jl;
            const float sqj = ssqj[jl];
            const int tj = stj[jl];
            float a0 = 0, a1 = 0, a2 = 0, a3 = 0, b0 = 0, b1 = 0, b2 = 0, b3 = 0;
#pragma unroll
            for (int mt = 0; mt < 2; mt++)
#pragma unroll
                for (int h = 0; h < 2; h++) {
                    const int il = wm * 32 + mt * 16 + h * 8 + qrow;
                    const int gi = i0 + il;
                    const bool kp = (!strad) || (gj > gi);
                    CELL(gi, gj, cfr[mt][nt][h * 2 + col], ssqi[il], sqj,
                         (sti[il] == tj), kp);
                }
            RED8(4);
            RED8(8);
            RED8(16);
            if (qrow == 0) {
                float* s = &sacc_j[jl * 8];
                atomicAdd(s + 0, a0); atomicAdd(s + 1, b0);
                atomicAdd(s + 2, a1); atomicAdd(s + 3, b1);
                atomicAdd(s + 4, a2); atomicAdd(s + 5, b2);
                atomicAdd(s + 6, a3); atomicAdd(s + 7, b3);
            }
        }
    __syncthreads();

    for (int v = tid; v < 1024; v += 256)
        atomicAdd(&g_acc[(size_t)(i0 + (v >> 3)) * 8 + (v & 7)], sacc_i[v]);
    for (int v = tid; v < 512; v += 256)
        atomicAdd(&g_acc[(size_t)(j0 + (v >> 3)) * 8 + (v & 7)], sacc_j[v]);
#undef CELL
#undef RED8

    // ---------------- last-CTA final reduction ----------------
    __threadfence();
    __shared__ unsigned int s_last;
    __syncthreads();
    if (tid == 0) s_last = atomicAdd(&g_ticket, 1u);
    __syncthreads();
    if (s_last != (unsigned int)(gridDim.x - 1)) return;
    __threadfence();

    float lsum = 0.f, pd = 0.f, nd = 0.f, pc = 0.f, nc = 0.f;
    for (int r = tid; r < n; r += 256) {
        const float* a = &g_acc[r * 8];
        float pl = a[0], nl = a[1], pb = a[2], nbv = a[3];
        float alr = 1.f - pl / (pl + nl);
        lsum += alr * (logf(pb) + logf(nbv));
        pd += a[4]; nd += a[5]; pc += a[6]; nc += a[7];
    }
    float* red = (float*)smem;    // reuse (post-barrier)
#pragma unroll
    for (int o = 16; o > 0; o >>= 1) {
        lsum += __shfl_xor_sync(0xffffffffu, lsum, o);
        pd += __shfl_xor_sync(0xffffffffu, pd, o);
        nd += __shfl_xor_sync(0xffffffffu, nd, o);
        pc += __shfl_xor_sync(0xffffffffu, pc, o);
        nc += __shfl_xor_sync(0xffffffffu, nc, o);
    }
    __syncthreads();
    if (lane == 0) {
        red[wid * 5 + 0] = lsum; red[wid * 5 + 1] = pd; red[wid * 5 + 2] = nd;
        red[wid * 5 + 3] = pc;   red[wid * 5 + 4] = nc;
    }
    __syncthreads();
    if (wid == 0) {
        float v0 = (lane < 8) ? red[lane * 5 + 0] : 0.f;
        float v1 = (lane < 8) ? red[lane * 5 + 1] : 0.f;
        float v2 = (lane < 8) ? red[lane * 5 + 2] : 0.f;
        float v3 = (lane < 8) ? red[lane * 5 + 3] : 0.f;
        float v4 = (lane < 8) ? red[lane * 5 + 4] : 0.f;
#pragma unroll
        for (int o = 4; o > 0; o >>= 1) {
            v0 += __shfl_xor_sync(0xffffffffu, v0, o);
            v1 += __shfl_xor_sync(0xffffffffu, v1, o);
            v2 += __shfl_xor_sync(0xffffffffu, v2, o);
            v3 += __shfl_xor_sync(0xffffffffu, v3, o);
            v4 += __shfl_xor_sync(0xffffffffu, v4, o);
        }
        if (lane == 0) {
            out[0] = v0 / (float)n;   // loss
            out[1] = 0.f;             // accuracy
            out[2] = v1 / v3;         // pos_d
            out[3] = v2 / v4;         // neg_d
        }
    }
}

// ---------------------------------------------------------------------------
extern "C" void kernel_launch(void* const* d_in, const int* in_sizes, int n_in,
                              void* d_out, int out_size) {
    const float* X = (const float*)d_in[0];
    const int* Tg = (const int*)d_in[1];
    int n = in_sizes[1];
    int d = in_sizes[0] / n;

    cudaFuncSetAttribute(pair_kernel, cudaFuncAttributeMaxDynamicSharedMemorySize, SMEM_DYN);

    prep_kernel<<<(n + 7) / 8, 256>>>(X, n, d);
    int nbi = n / BTM;                         // 32
    int nbj = n / BTN;                         // 64
    int ntiles = nbi * nbj - nbi * (nbi - 1);  // sum over bi of (nbj - 2*bi) = 1056
    pair_kernel<<<ntiles, 256, SMEM_DYN>>>(Tg, nbj, (float*)d_out, n);
}

// round 16
// speedup vs baseline: 1.1779x; 1.1779x over previous
#include <cuda_runtime.h>
#include <cuda_fp16.h>
#include <math.h>
#include <stdint.h>

#define N_MAX 4096
#define D_DIM 1024
#define BT 128
#define BK 64
#define STRIDE 72                              // fp16 elems per smem row (64 data + 8 pad)
#define ROWB (STRIDE * 2)                      // 144 bytes per row
#define MAT_BYTES (BT * ROWB)                  // 18432
#define STAGE_BYTES (2 * MAT_BYTES)            // A,B = 36864
#define NSTAGE 2
#define SMEM_DYN (NSTAGE * STAGE_BYTES)        // 73728
#define NCHUNK (D_DIM / BK)                    // 16

// Per-row accumulators: [0]=pos_logit [1]=neg_logit [2]=pos_beta [3]=neg_beta
__device__ float g_acc[N_MAX * 4];
// global scalars: [0]=pos_d_sum [1]=neg_d_sum [2]=pos_cnt [3]=neg_cnt
__device__ float g_scal[4];
__device__ float g_sq[N_MAX];
__device__ __half g_h[N_MAX * D_DIM];
__device__ unsigned int g_ticket;

// ---------------------------------------------------------------------------
__device__ __forceinline__ uint32_t smem_u32(const void* p) {
    uint32_t a;
    asm("{ .reg .u64 t; cvta.to.shared.u64 t, %1; cvt.u32.u64 %0, t; }" : "=r"(a) : "l"(p));
    return a;
}
__device__ __forceinline__ void cp16(uint32_t dst, const void* src) {
    asm volatile("cp.async.cg.shared.global [%0], [%1], 16;" :: "r"(dst), "l"(src) : "memory");
}
__device__ __forceinline__ void ldsm4(uint32_t& r0, uint32_t& r1, uint32_t& r2, uint32_t& r3,
                                      uint32_t addr) {
    asm volatile("ldmatrix.sync.aligned.m8n8.x4.shared.b16 {%0,%1,%2,%3}, [%4];"
                 : "=r"(r0), "=r"(r1), "=r"(r2), "=r"(r3) : "r"(addr));
}
__device__ __forceinline__ void mma16816(float* c, const uint32_t* a, const uint32_t* b) {
    asm volatile(
        "mma.sync.aligned.m16n8k16.row.col.f32.f16.f16.f32 "
        "{%0,%1,%2,%3}, {%4,%5,%6,%7}, {%8,%9}, {%0,%1,%2,%3};"
        : "+f"(c[0]), "+f"(c[1]), "+f"(c[2]), "+f"(c[3])
        : "r"(a[0]), "r"(a[1]), "r"(a[2]), "r"(a[3]), "r"(b[0]), "r"(b[1]));
}
__device__ __forceinline__ float fsqrt_ap(float x) {
    float r;
    asm("sqrt.approx.f32 %0, %1;" : "=f"(r) : "f"(x));
    return r;
}

// ---------------------------------------------------------------------------
// prep: fp16 convert, row norms, zero accumulators + scalars + ticket.
// ---------------------------------------------------------------------------
__global__ void prep_kernel(const float* __restrict__ X, int n, int d) {
    const int w = threadIdx.x >> 5;
    const int lane = threadIdx.x & 31;
    const int r = blockIdx.x * 8 + w;
    if (blockIdx.x == 0 && threadIdx.x < 5) {
        if (threadIdx.x == 4) g_ticket = 0u;
        else g_scal[threadIdx.x] = 0.f;
    }
    if (r >= n) return;
    const float4* xr = (const float4*)(X + (size_t)r * d);

    float4 v[8];
#pragma unroll
    for (int i = 0; i < 8; i++) v[i] = xr[lane + i * 32];

    float s = 0.f;
#pragma unroll
    for (int i = 0; i < 8; i++) {
        s = fmaf(v[i].x, v[i].x, s);
        s = fmaf(v[i].y, v[i].y, s);
        s = fmaf(v[i].z, v[i].z, s);
        s = fmaf(v[i].w, v[i].w, s);
    }

#pragma unroll
    for (int i = 0; i < 8; i++) {
        __half h[4] = {__float2half(v[i].x), __float2half(v[i].y),
                       __float2half(v[i].z), __float2half(v[i].w)};
        *(ushort4*)&g_h[(size_t)r * d + (lane + i * 32) * 4] = *(ushort4*)h;
    }

#pragma unroll
    for (int o = 16; o > 0; o >>= 1) s += __shfl_xor_sync(0xffffffffu, s, o);
    if (lane == 0) g_sq[r] = s;
    if (lane < 4) g_acc[r * 4 + lane] = 0.f;
}

// ---------------------------------------------------------------------------
// pair kernel: upper-triangle 128x128 tiles, single-pass fp16 Gram.
// 2-stage cp.async ring, barrier per BK=64 chunk; odd warps process the 4
// k16 steps rotated by 2 (legal: accumulation is order-free) to decorrelate
// post-barrier ldsm bursts. Slim epilogue: 4 shuffled per-row stats; dist
// sums and counts go thread-local -> warp-reduce -> 4 global scalars.
// Last CTA (ticket) does the final [4]-output reduction.
// ---------------------------------------------------------------------------
__global__ __launch_bounds__(256, 2) void pair_kernel(const int* __restrict__ Tg, int nb,
                                                      float* __restrict__ out, int n) {
    extern __shared__ __align__(16) char smem[];

    // triangular decode
    int t = blockIdx.x, bi = 0;
    while (t >= nb - bi) { t -= nb - bi; bi++; }
    const int bj = bi + t;
    const bool diag = (bi == bj);
    const int i0 = bi * BT, j0 = bj * BT;

    const int tid = threadIdx.x;
    const int lane = tid & 31;
    const int wid = tid >> 5;
    const int wm = wid & 1;        // warp row: 64 rows each
    const int wn = wid >> 1;       // warp col: 32 cols each

    const uint32_t sb = smem_u32(smem);

    // per-thread load geometry, hoisted
    uint32_t so[4];
    const __half *gA[4], *gB[4];
#pragma unroll
    for (int it = 0; it < 4; it++) {
        const int u = tid + it * 256;
        const int row = u >> 3, q = u & 7;
        so[it] = (uint32_t)(row * ROWB + q * 16);
        gA[it] = g_h + (size_t)(i0 + row) * D_DIM + q * 8;
        gB[it] = g_h + (size_t)(j0 + row) * D_DIM + q * 8;
    }

    float cfr[4][4][4];
#pragma unroll
    for (int a = 0; a < 4; a++)
#pragma unroll
        for (int b = 0; b < 4; b++)
#pragma unroll
            for (int c = 0; c < 4; c++) cfr[a][b][c] = 0.f;

    auto issue = [&](int c) {
        const int k0 = c * BK;
        const uint32_t st = sb + (uint32_t)(c & (NSTAGE - 1)) * STAGE_BYTES;
#pragma unroll
        for (int it = 0; it < 4; it++) {
            cp16(st + so[it], gA[it] + k0);
            cp16(st + MAT_BYTES + so[it], gB[it] + k0);
        }
        asm volatile("cp.async.commit_group;" ::: "memory");
    };

    const int srot = (wid & 1) << 1;           // odd warps start at step 2

    issue(0);
#pragma unroll 1
    for (int c = 0; c < NCHUNK; c++) {
        asm volatile("cp.async.wait_group 0;" ::: "memory");   // own cp landed
        __syncthreads();                                       // publish + WAR guard
        if (c + 1 < NCHUNK) issue(c + 1);                      // overlaps compute(c)

        const uint32_t st = sb + (uint32_t)(c & (NSTAGE - 1)) * STAGE_BYTES;
        const uint32_t aB = st, bB = st + MAT_BYTES;
        const int gl = lane >> 3;
        const uint32_t aRow = (uint32_t)(wm * 64 + (lane & 15)) * ROWB;
        const uint32_t bRow = (uint32_t)(wn * 32 + ((gl >> 1) << 3) + (lane & 7)) * ROWB;
        const uint32_t aKo = (uint32_t)((lane >> 4) << 3) * 2;
        const uint32_t bKo = (uint32_t)((gl & 1) << 3) * 2;
#pragma unroll
        for (int s0 = 0; s0 < 4; s0++) {                       // 4 k16 steps, staggered
            const int s = (s0 + srot) & 3;
            const uint32_t k0 = (uint32_t)(s * 16) * 2;
            uint32_t af[4][4], bf[4][2];
#pragma unroll
            for (int mt = 0; mt < 4; mt++) {
                const uint32_t ro = aRow + (uint32_t)(mt * 16) * ROWB + k0 + aKo;
                ldsm4(af[mt][0], af[mt][1], af[mt][2], af[mt][3], aB + ro);
            }
#pragma unroll
            for (int g = 0; g < 2; g++) {
                const uint32_t ro = bRow + (uint32_t)(g * 16) * ROWB + k0 + bKo;
                ldsm4(bf[2 * g][0], bf[2 * g][1], bf[2 * g + 1][0], bf[2 * g + 1][1], bB + ro);
            }
#pragma unroll
            for (int mt = 0; mt < 4; mt++)
#pragma unroll
                for (int nt = 0; nt < 4; nt++) mma16816(cfr[mt][nt], af[mt], bf[nt]);
        }
    }
    __syncthreads();

    // ---------------- epilogue (aliases the tile smem) ----------------
    float* sacc_i = (float*)smem;          // 512 f
    float* sacc_j = sacc_i + 512;          // 512 f
    float* ssqi = sacc_j + 512;            // 128 f
    float* ssqj = ssqi + 128;              // 128 f
    int* sti = (int*)(ssqj + 128);         // 128 i
    int* stj = sti + 128;                  // 128 i

    for (int v = tid; v < 1024; v += 256) sacc_i[v] = 0.f;
    if (tid < 128) {
        ssqi[tid] = g_sq[i0 + tid];
        sti[tid] = Tg[i0 + tid];
    } else {
        const int q = tid - 128;
        ssqj[q] = g_sq[j0 + q];
        stj[q] = Tg[j0 + q];
    }
    __syncthreads();

    const float E2 = 7.3890560989306495f;
    const float E4 = 54.598150033144236f;
    const int qrow = lane >> 2, qcol = lane & 3;

    float pdl = 0.f, ndl = 0.f, pcl = 0.f, ncl = 0.f;   // thread-local scalar sums

#define CELL(DOT, SQI, SQJ, SAME, SELF)                                              \
    {                                                                                \
        float d2 = fmaf(-2.f, (DOT), (SQI) + (SQJ));                                 \
        float dist = fsqrt_ap(fmaxf(d2, 1e-12f));                                    \
        float tt = __expf(20.f * (1.f - dist));                                      \
        float ea = tt * tt;                                                          \
        if (SAME) {                                                                  \
            if (!(SELF)) {                                                           \
                a0 += ea; a1 += __fdividef(E4, tt); pdl += dist; pcl += 1.f;         \
            }                                                                        \
        } else {                                                                     \
            b0 += ea; b1 += E2 * tt; ndl += dist; ncl += 1.f;                        \
        }                                                                            \
    }

#define RED4(OFF)                                                 \
    {                                                             \
        a0 += __shfl_xor_sync(0xffffffffu, a0, OFF);              \
        a1 += __shfl_xor_sync(0xffffffffu, a1, OFF);              \
        b0 += __shfl_xor_sync(0xffffffffu, b0, OFF);              \
        b1 += __shfl_xor_sync(0xffffffffu, b1, OFF);              \
    }

    // i-oriented pass
#pragma unroll
    for (int mt = 0; mt < 4; mt++)
#pragma unroll
        for (int h = 0; h < 2; h++) {
            const int il = wm * 64 + mt * 16 + h * 8 + qrow;
            const float sqi = ssqi[il];
            const int ti = sti[il];
            float a0 = 0, a1 = 0, b0 = 0, b1 = 0;
#pragma unroll
            for (int nt = 0; nt < 4; nt++)
#pragma unroll
                for (int col = 0; col < 2; col++) {
                    const int jl = wn * 32 + nt * 8 + 2 * qcol + col;
                    CELL(cfr[mt][nt][h * 2 + col], sqi, ssqj[jl],
                         (ti == stj[jl]), (diag && il == jl));
                }
            RED4(1);
            RED4(2);
            if (qcol == 0) {
                // layout: [0]=pos_logit [1]=neg_logit [2]=pos_beta [3]=neg_beta
                float* s = &sacc_i[il * 4];
                atomicAdd(s + 0, a0); atomicAdd(s + 1, b0);
                atomicAdd(s + 2, a1); atomicAdd(s + 3, b1);
            }
        }

    // j-oriented pass (off-diagonal tiles only; symmetric contribution)
    if (!diag) {
#pragma unroll
        for (int nt = 0; nt < 4; nt++)
#pragma unroll
            for (int col = 0; col < 2; col++) {
                const int jl = wn * 32 + nt * 8 + 2 * qcol + col;
                const float sqj = ssqj[jl];
                const int tj = stj[jl];
                float a0 = 0, a1 = 0, b0 = 0, b1 = 0;
#pragma unroll
                for (int mt = 0; mt < 4; mt++)
#pragma unroll
                    for (int h = 0; h < 2; h++) {
                        const int il = wm * 64 + mt * 16 + h * 8 + qrow;
                        CELL(cfr[mt][nt][h * 2 + col], ssqi[il], sqj,
                             (sti[il] == tj), false);
                    }
                RED4(4);
                RED4(8);
                RED4(16);
                if (qrow == 0) {
                    float* s = &sacc_j[jl * 4];
                    atomicAdd(s + 0, a0); atomicAdd(s + 1, b0);
                    atomicAdd(s + 2, a1); atomicAdd(s + 3, b1);
                }
            }
    }

    // scalar sums: warp-reduce then one global atomic per warp
#pragma unroll
    for (int o = 16; o > 0; o >>= 1) {
        pdl += __shfl_xor_sync(0xffffffffu, pdl, o);
        ndl += __shfl_xor_sync(0xffffffffu, ndl, o);
        pcl += __shfl_xor_sync(0xffffffffu, pcl, o);
        ncl += __shfl_xor_sync(0xffffffffu, ncl, o);
    }
    if (lane == 0) {
        atomicAdd(&g_scal[0], pdl);
        atomicAdd(&g_scal[1], ndl);
        atomicAdd(&g_scal[2], pcl);
        atomicAdd(&g_scal[3], ncl);
    }
    __syncthreads();

    for (int v = tid; v < 512; v += 256)
        atomicAdd(&g_acc[(size_t)(i0 + (v >> 2)) * 4 + (v & 3)], sacc_i[v]);
    if (!diag)
        for (int v = tid; v < 512; v += 256)
            atomicAdd(&g_acc[(size_t)(j0 + (v >> 2)) * 4 + (v & 3)], sacc_j[v]);
#undef CELL
#undef RED4

    // ---------------- last-CTA final reduction ----------------
    __threadfence();
    __shared__ unsigned int s_last;
    __syncthreads();
    if (tid == 0) s_last = atomicAdd(&g_ticket, 1u);
    __syncthreads();
    if (s_last != (unsigned int)(gridDim.x - 1)) return;
    __threadfence();

    float lsum = 0.f;
    for (int r = tid; r < n; r += 256) {
        const float* a = &g_acc[r * 4];
        // layout: [0]=pos_logit [1]=neg_logit [2]=pos_beta [3]=neg_beta
        float pl = a[0], nl = a[1], pb = a[2], nbv = a[3];
        float alr = 1.f - pl / (pl + nl);
        lsum += alr * (logf(pb) + logf(nbv));
    }
    float* red = (float*)smem;    // reuse (post-barrier)
#pragma unroll
    for (int o = 16; o > 0; o >>= 1)
        lsum += __shfl_xor_sync(0xffffffffu, lsum, o);
    __syncthreads();
    if (lane == 0) red[wid] = lsum;
    __syncthreads();
    if (tid == 0) {
        float v0 = 0.f;
#pragma unroll
        for (int i = 0; i < 8; i++) v0 += red[i];
        out[0] = v0 / (float)n;                 // loss
        out[1] = 0.f;                           // accuracy
        out[2] = g_scal[0] / g_scal[2];         // pos_d
        out[3] = g_scal[1] / g_scal[3];         // neg_d
    }
}

// ---------------------------------------------------------------------------
extern "C" void kernel_launch(void* const* d_in, const int* in_sizes, int n_in,
                              void* d_out, int out_size) {
    const float* X = (const float*)d_in[0];
    const int* Tg = (const int*)d_in[1];
    int n = in_sizes[1];
    int d = in_sizes[0] / n;

    cudaFuncSetAttribute(pair_kernel, cudaFuncAttributeMaxDynamicSharedMemorySize, SMEM_DYN);

    prep_kernel<<<(n + 7) / 8, 256>>>(X, n, d);
    int nb = n / BT;
    int ntiles = nb * (nb + 1) / 2;
    pair_kernel<<<ntiles, 256, SMEM_DYN>>>(Tg, nb, (float*)d_out, n);
}